// round 6
// baseline (speedup 1.0000x reference)
#include <cuda_runtime.h>
#include <cuda_fp16.h>
#include <cuda_bf16.h>

#define NN 50000
#define NE 800000
#define HD 128
#define NMAT 14
#define NSB 49   // scan blocks: ceil(50000/1024)
#define SAW 136  // A smem row stride (halves): 128 + 8 pad
#define SBW 40   // B smem row stride (halves): 32 + 8 pad

// ---------------- device scratch (no allocations allowed) ----------------
__device__ __half  g_yA[(size_t)NN * HD];   // fp16 message ping
__device__ __half  g_yB[(size_t)NN * HD];   // fp16 message pong
__device__ float   g_x[(size_t)NN * HD];    // running x (fp32)
__device__ float   g_norm[NN];
__device__ int     g_rowptr[NN + 1];
__device__ int     g_cnt[NN];
__device__ int     g_off[NN];
__device__ int     g_col[NE];
__device__ int     g_bsum[NSB];
__device__ __nv_bfloat16 g_wh[(size_t)NMAT * HD * HD];  // weights, n-major, hi part
__device__ __nv_bfloat16 g_wl[(size_t)NMAT * HD * HD];  // lo part

__device__ __forceinline__ float lk(float v) { return v >= 0.f ? v : 0.01f * v; }

__device__ __forceinline__ float2 u2f2(unsigned u) {
    __half2 h = *reinterpret_cast<__half2*>(&u);
    return __half22float2(h);
}

// ---------------- CSR build ----------------
__global__ void count_kernel(const int* __restrict__ dst) {
    int e = blockIdx.x * blockDim.x + threadIdx.x;
    if (e < NE) atomicAdd(&g_cnt[dst[e]], 1);
}

__global__ __launch_bounds__(1024) void scan_blocks_kernel() {
    __shared__ int ws[32];
    int tid = threadIdx.x, lane = tid & 31, wid = tid >> 5;
    int i = blockIdx.x * 1024 + tid;
    int v = (i < NN) ? g_cnt[i] : 0;
    int x = v;
#pragma unroll
    for (int d = 1; d < 32; d <<= 1) {
        int t = __shfl_up_sync(0xffffffffu, x, d);
        if (lane >= d) x += t;
    }
    if (lane == 31) ws[wid] = x;
    __syncthreads();
    if (wid == 0) {
        int s = ws[lane];
#pragma unroll
        for (int d = 1; d < 32; d <<= 1) {
            int t = __shfl_up_sync(0xffffffffu, s, d);
            if (lane >= d) s += t;
        }
        ws[lane] = s;
    }
    __syncthreads();
    int off = wid ? ws[wid - 1] : 0;
    if (i < NN) g_rowptr[i] = off + x - v;
    if (tid == 1023) g_bsum[blockIdx.x] = off + x;
}

__global__ void scan_tops_kernel() {
    int lane = threadIdx.x;
    int carry = 0;
    for (int base = 0; base < NSB; base += 32) {
        int i = base + lane;
        int v = (i < NSB) ? g_bsum[i] : 0;
        int x = v;
#pragma unroll
        for (int d = 1; d < 32; d <<= 1) {
            int t = __shfl_up_sync(0xffffffffu, x, d);
            if (lane >= d) x += t;
        }
        if (i < NSB) g_bsum[i] = carry + x - v;
        carry += __shfl_sync(0xffffffffu, x, 31);
    }
    if (lane == 0) g_rowptr[NN] = NE;
}

__global__ __launch_bounds__(1024) void scan_fix_kernel() {
    int i = blockIdx.x * 1024 + threadIdx.x;
    if (i < NN) {
        int r = g_rowptr[i] + g_bsum[blockIdx.x];
        g_rowptr[i] = r;
        g_off[i] = r;
        g_norm[i] = rsqrtf(1.0f + (float)g_cnt[i]);
    }
}

__global__ void fill_kernel(const int* __restrict__ src, const int* __restrict__ dst) {
    int e = blockIdx.x * blockDim.x + threadIdx.x;
    if (e < NE) {
        int d = dst[e];
        int p = atomicAdd(&g_off[d], 1);
        g_col[p] = src[e];
    }
}

// ---------------- weight prep: transpose to n-major, split fp32 -> bf16 hi/lo ----
__global__ void prep_w_kernel(const float* __restrict__ w_in, const float* __restrict__ w1,
                              const float* __restrict__ w2, const float* __restrict__ w_out) {
    int idx = blockIdx.x * blockDim.x + threadIdx.x;
    if (idx >= NMAT * HD * HD) return;
    int mat = idx >> 14;
    int rem = idx & 16383;
    int n = rem >> 7, k = rem & 127;
    float v;
    if (mat == 0)       v = w_in[k * HD + n];
    else if (mat <= 6)  v = w1[(size_t)(mat - 1) * HD * HD + k * HD + n];
    else if (mat <= 12) v = w2[(size_t)(mat - 7) * HD * HD + k * HD + n];
    else                v = (n < 64) ? w_out[k * 64 + n] : 0.f;
    __nv_bfloat16 hi = __float2bfloat16(v);
    __nv_bfloat16 lo = __float2bfloat16(v - __bfloat162float(hi));
    g_wh[idx] = hi;
    g_wl[idx] = lo;
}

// ---------------- bf16x2 split MMA helper ----------------
__device__ __forceinline__ void mma_bf16(float* c, unsigned a0, unsigned a1, unsigned a2,
                                         unsigned a3, unsigned b0, unsigned b1) {
    asm volatile(
        "mma.sync.aligned.m16n8k16.row.col.f32.bf16.bf16.f32 "
        "{%0,%1,%2,%3}, {%4,%5,%6,%7}, {%8,%9}, {%0,%1,%2,%3};"
        : "+f"(c[0]), "+f"(c[1]), "+f"(c[2]), "+f"(c[3])
        : "r"(a0), "r"(a1), "r"(a2), "r"(a3), "r"(b0), "r"(b1));
}

// ---------------- standalone GEMM (first conv, A = fp32 inputs) ----------------
// Yh[m,:] = half( (A[m,:] @ W) * norm[m] ), BN = 128, K = 128, static smem BK=32.
__global__ __launch_bounds__(256) void gemm_tc_kernel(const float* __restrict__ A,
                                                      const __nv_bfloat16* __restrict__ Wh,
                                                      const __nv_bfloat16* __restrict__ Wl,
                                                      __half* __restrict__ Yh) {
    constexpr int BM = 128, BK = 32, K = 128, BN = 128;
    constexpr int SA = 40;
    __shared__ __nv_bfloat16 sAh[BM * SA], sAl[BM * SA];
    __shared__ __nv_bfloat16 sBh[BN * SA], sBl[BN * SA];

    const int tid = threadIdx.x, lane = tid & 31, wid = tid >> 5;
    const int g = lane >> 2, t = lane & 3;
    const int wm = (wid & 1) * 64, wn = (wid >> 1) * 32;
    const int m0 = blockIdx.x * BM;

    float acc[4][4][4];
#pragma unroll
    for (int i = 0; i < 4; i++)
#pragma unroll
        for (int j = 0; j < 4; j++)
#pragma unroll
            for (int q = 0; q < 4; q++) acc[i][j][q] = 0.f;

    float4 va[4];
    uint4 vbh[2], vbl[2];

    auto loadA = [&](int k0) {
#pragma unroll
        for (int l = 0; l < 4; l++) {
            int idx = tid + l * 256, r = idx >> 3, c = idx & 7;
            va[l] = make_float4(0.f, 0.f, 0.f, 0.f);
            if (m0 + r < NN) va[l] = *(const float4*)(A + (size_t)(m0 + r) * K + k0 + c * 4);
        }
    };
    auto loadB = [&](int k0) {
        int n = tid >> 1, kh = (tid & 1) * 16;
        vbh[0] = *(const uint4*)&Wh[(size_t)n * K + k0 + kh];
        vbh[1] = *(const uint4*)&Wh[(size_t)n * K + k0 + kh + 8];
        vbl[0] = *(const uint4*)&Wl[(size_t)n * K + k0 + kh];
        vbl[1] = *(const uint4*)&Wl[(size_t)n * K + k0 + kh + 8];
    };
    auto storeTiles = [&]() {
#pragma unroll
        for (int l = 0; l < 4; l++) {
            int idx = tid + l * 256, r = idx >> 3, c = idx & 7;
            float4 v = va[l];
            __nv_bfloat16 h0 = __float2bfloat16(v.x), h1 = __float2bfloat16(v.y);
            __nv_bfloat16 h2 = __float2bfloat16(v.z), h3 = __float2bfloat16(v.w);
            __nv_bfloat162 p01, p23, q01, q23;
            p01.x = h0; p01.y = h1; p23.x = h2; p23.y = h3;
            q01.x = __float2bfloat16(v.x - __bfloat162float(h0));
            q01.y = __float2bfloat16(v.y - __bfloat162float(h1));
            q23.x = __float2bfloat16(v.z - __bfloat162float(h2));
            q23.y = __float2bfloat16(v.w - __bfloat162float(h3));
            *(__nv_bfloat162*)&sAh[r * SA + c * 4]     = p01;
            *(__nv_bfloat162*)&sAh[r * SA + c * 4 + 2] = p23;
            *(__nv_bfloat162*)&sAl[r * SA + c * 4]     = q01;
            *(__nv_bfloat162*)&sAl[r * SA + c * 4 + 2] = q23;
        }
        int n = tid >> 1, kh = (tid & 1) * 16;
        *(uint4*)&sBh[n * SA + kh]     = vbh[0];
        *(uint4*)&sBh[n * SA + kh + 8] = vbh[1];
        *(uint4*)&sBl[n * SA + kh]     = vbl[0];
        *(uint4*)&sBl[n * SA + kh + 8] = vbl[1];
    };

    loadA(0);
    loadB(0);
    for (int k0 = 0; k0 < K; k0 += BK) {
        storeTiles();
        __syncthreads();
        if (k0 + BK < K) { loadA(k0 + BK); loadB(k0 + BK); }
#pragma unroll
        for (int kk = 0; kk < BK; kk += 16) {
            unsigned bh[4][2], bl[4][2];
#pragma unroll
            for (int nt = 0; nt < 4; nt++) {
                int n = wn + nt * 8 + g;
                bh[nt][0] = *(const unsigned*)&sBh[n * SA + kk + 2 * t];
                bh[nt][1] = *(const unsigned*)&sBh[n * SA + kk + 2 * t + 8];
                bl[nt][0] = *(const unsigned*)&sBl[n * SA + kk + 2 * t];
                bl[nt][1] = *(const unsigned*)&sBl[n * SA + kk + 2 * t + 8];
            }
#pragma unroll
            for (int mt = 0; mt < 4; mt++) {
                int m = wm + mt * 16 + g;
                unsigned ah0 = *(const unsigned*)&sAh[m * SA + kk + 2 * t];
                unsigned ah1 = *(const unsigned*)&sAh[(m + 8) * SA + kk + 2 * t];
                unsigned ah2 = *(const unsigned*)&sAh[m * SA + kk + 2 * t + 8];
                unsigned ah3 = *(const unsigned*)&sAh[(m + 8) * SA + kk + 2 * t + 8];
                unsigned al0 = *(const unsigned*)&sAl[m * SA + kk + 2 * t];
                unsigned al1 = *(const unsigned*)&sAl[(m + 8) * SA + kk + 2 * t];
                unsigned al2 = *(const unsigned*)&sAl[m * SA + kk + 2 * t + 8];
                unsigned al3 = *(const unsigned*)&sAl[(m + 8) * SA + kk + 2 * t + 8];
#pragma unroll
                for (int nt = 0; nt < 4; nt++) {
                    mma_bf16(acc[mt][nt], ah0, ah1, ah2, ah3, bh[nt][0], bh[nt][1]);
                    mma_bf16(acc[mt][nt], ah0, ah1, ah2, ah3, bl[nt][0], bl[nt][1]);
                    mma_bf16(acc[mt][nt], al0, al1, al2, al3, bh[nt][0], bh[nt][1]);
                }
            }
        }
        __syncthreads();
    }

#pragma unroll
    for (int mt = 0; mt < 4; mt++) {
        int r0 = m0 + wm + mt * 16 + g, r1 = r0 + 8;
        float n0 = (r0 < NN) ? g_norm[r0] : 0.f;
        float n1 = (r1 < NN) ? g_norm[r1] : 0.f;
#pragma unroll
        for (int nt = 0; nt < 4; nt++) {
            int col = wn + nt * 8 + 2 * t;
            if (r0 < NN) {
                __half2 h = __floats2half2_rn(acc[mt][nt][0] * n0, acc[mt][nt][1] * n0);
                *(__half2*)(Yh + (size_t)r0 * BN + col) = h;
            }
            if (r1 < NN) {
                __half2 h = __floats2half2_rn(acc[mt][nt][2] * n1, acc[mt][nt][3] * n1);
                *(__half2*)(Yh + (size_t)r1 * BN + col) = h;
            }
        }
    }
}

// ---------------- FUSED agg + GEMM ----------------
// Phase 1 (agg): 8 warps x 16 rows. For each row r of this block's 128 rows:
//   o = norm[r]*(Yin[r] + sum_{src->r} Yin[src]) + bias
//   MODE 0: a = leaky(o), write x
//   MODE 2: a = leaky(o)              (intermediate h: never touches gmem)
//   MODE 1: a = (x + leaky(o))*0.5, rw x
//   MODE 3: MODE 1 + mirror a to out2
// a is split to bf16 hi/lo directly into GEMM A-smem (full K=128 resident).
// Phase 2 (GEMM): Yout[r,:] = half( (a @ W) * norm[r] ), B streamed BK=32 x2 buf.
template <int BN, int MODE>
__global__ __launch_bounds__(256, 2) void fused_kernel(
    const __half* __restrict__ Yin, const float* __restrict__ bias,
    float* __restrict__ xbuf, float* __restrict__ out2,
    const __nv_bfloat16* __restrict__ Wh, const __nv_bfloat16* __restrict__ Wl,
    __half* __restrict__ Yout) {
    constexpr int K = 128;
    constexpr int WN = BN / 4, NT = WN / 8;
    extern __shared__ __nv_bfloat16 sm[];
    __nv_bfloat16* sAh = sm;                       // 128*SAW
    __nv_bfloat16* sAl = sAh + 128 * SAW;
    __nv_bfloat16* sBh = sAl + 128 * SAW;          // 2 stages * BN*SBW
    __nv_bfloat16* sBl = sBh + 2 * BN * SBW;

    const int tid = threadIdx.x, lane = tid & 31, wid = tid >> 5;
    const int g = lane >> 2, t = lane & 3;
    const int wm = (wid & 1) * 64, wn = (wid >> 1) * WN;
    const int m0 = blockIdx.x * 128;
    const int* __restrict__ col = g_col;

    // ---------- phase 1: aggregation ----------
    {
        const uint2* Y4 = (const uint2*)Yin;
        float4 b4 = ((const float4*)bias)[lane];
        for (int i = 0; i < 16; i++) {
            int rloc = wid * 16 + i;
            int r = m0 + rloc;
            float4 a = make_float4(0.f, 0.f, 0.f, 0.f);
            if (r < NN) {
                int beg = g_rowptr[r], end = g_rowptr[r + 1];
                uint2 sv = Y4[(size_t)r * 32 + lane];
                float2 f0 = u2f2(sv.x), f1 = u2f2(sv.y);
                float4 acc = make_float4(f0.x, f0.y, f1.x, f1.y);
                int e = beg;
#define ACC8(vv) { float2 p = u2f2(vv.x), q = u2f2(vv.y); \
                   acc.x += p.x; acc.y += p.y; acc.z += q.x; acc.w += q.y; }
                for (; e + 7 < end; e += 8) {
                    int s0 = col[e],     s1 = col[e + 1], s2 = col[e + 2], s3 = col[e + 3];
                    int s4 = col[e + 4], s5 = col[e + 5], s6 = col[e + 6], s7 = col[e + 7];
                    uint2 v0 = Y4[(size_t)s0 * 32 + lane];
                    uint2 v1 = Y4[(size_t)s1 * 32 + lane];
                    uint2 v2 = Y4[(size_t)s2 * 32 + lane];
                    uint2 v3 = Y4[(size_t)s3 * 32 + lane];
                    uint2 v4 = Y4[(size_t)s4 * 32 + lane];
                    uint2 v5 = Y4[(size_t)s5 * 32 + lane];
                    uint2 v6 = Y4[(size_t)s6 * 32 + lane];
                    uint2 v7 = Y4[(size_t)s7 * 32 + lane];
                    ACC8(v0) ACC8(v1) ACC8(v2) ACC8(v3)
                    ACC8(v4) ACC8(v5) ACC8(v6) ACC8(v7)
                }
                for (; e < end; e++) {
                    uint2 v = Y4[(size_t)col[e] * 32 + lane];
                    ACC8(v)
                }
#undef ACC8
                float nm = g_norm[r];
                float4 o = make_float4(acc.x * nm + b4.x, acc.y * nm + b4.y,
                                       acc.z * nm + b4.z, acc.w * nm + b4.w);
                float4 l4 = make_float4(lk(o.x), lk(o.y), lk(o.z), lk(o.w));
                size_t xi = (size_t)r * 32 + lane;
                if constexpr (MODE == 0) {
                    a = l4;
                    ((float4*)xbuf)[xi] = a;
                } else if constexpr (MODE == 2) {
                    a = l4;
                } else {  // 1 or 3
                    float4 xr = ((const float4*)xbuf)[xi];
                    a = make_float4((xr.x + l4.x) * 0.5f, (xr.y + l4.y) * 0.5f,
                                    (xr.z + l4.z) * 0.5f, (xr.w + l4.w) * 0.5f);
                    ((float4*)xbuf)[xi] = a;
                    if constexpr (MODE == 3) ((float4*)out2)[xi] = a;
                }
            }
            // pack to bf16 hi/lo into A smem
            __nv_bfloat16 h0 = __float2bfloat16(a.x), h1 = __float2bfloat16(a.y);
            __nv_bfloat16 h2 = __float2bfloat16(a.z), h3 = __float2bfloat16(a.w);
            __nv_bfloat162 p01, p23, q01, q23;
            p01.x = h0; p01.y = h1; p23.x = h2; p23.y = h3;
            q01.x = __float2bfloat16(a.x - __bfloat162float(h0));
            q01.y = __float2bfloat16(a.y - __bfloat162float(h1));
            q23.x = __float2bfloat16(a.z - __bfloat162float(h2));
            q23.y = __float2bfloat16(a.w - __bfloat162float(h3));
            *(__nv_bfloat162*)&sAh[rloc * SAW + lane * 4]     = p01;
            *(__nv_bfloat162*)&sAh[rloc * SAW + lane * 4 + 2] = p23;
            *(__nv_bfloat162*)&sAl[rloc * SAW + lane * 4]     = q01;
            *(__nv_bfloat162*)&sAl[rloc * SAW + lane * 4 + 2] = q23;
        }
    }
    __syncthreads();

    // ---------- phase 2: GEMM ----------
    uint4 vbh[2], vbl[2];
    auto loadB = [&](int k0) {
        if constexpr (BN == 128) {
#pragma unroll
            for (int l = 0; l < 2; l++) {
                int idx = tid + l * 256, n = idx >> 2, kp = (idx & 3) * 8;
                vbh[l] = *(const uint4*)&Wh[(size_t)n * K + k0 + kp];
                vbl[l] = *(const uint4*)&Wl[(size_t)n * K + k0 + kp];
            }
        } else {
            int n = tid >> 2, kp = (tid & 3) * 8;
            vbh[0] = *(const uint4*)&Wh[(size_t)n * K + k0 + kp];
            vbl[0] = *(const uint4*)&Wl[(size_t)n * K + k0 + kp];
        }
    };
    auto storeB = [&](int buf) {
        if constexpr (BN == 128) {
#pragma unroll
            for (int l = 0; l < 2; l++) {
                int idx = tid + l * 256, n = idx >> 2, kp = (idx & 3) * 8;
                *(uint4*)&sBh[buf * BN * SBW + n * SBW + kp] = vbh[l];
                *(uint4*)&sBl[buf * BN * SBW + n * SBW + kp] = vbl[l];
            }
        } else {
            int n = tid >> 2, kp = (tid & 3) * 8;
            *(uint4*)&sBh[buf * BN * SBW + n * SBW + kp] = vbh[0];
            *(uint4*)&sBl[buf * BN * SBW + n * SBW + kp] = vbl[0];
        }
    };

    float acc[4][NT][4];
#pragma unroll
    for (int i = 0; i < 4; i++)
#pragma unroll
        for (int j = 0; j < NT; j++)
#pragma unroll
            for (int q = 0; q < 4; q++) acc[i][j][q] = 0.f;

    loadB(0);
    storeB(0);
    __syncthreads();
#pragma unroll
    for (int s = 0; s < 4; s++) {
        if (s < 3) loadB((s + 1) * 32);
        const int buf = s & 1, k0 = s * 32;
        const __nv_bfloat16* bhp = sBh + buf * BN * SBW;
        const __nv_bfloat16* blp = sBl + buf * BN * SBW;
#pragma unroll
        for (int kk = 0; kk < 32; kk += 16) {
            unsigned bh[NT][2], bl[NT][2];
#pragma unroll
            for (int nt = 0; nt < NT; nt++) {
                int n = wn + nt * 8 + g;
                bh[nt][0] = *(const unsigned*)&bhp[n * SBW + kk + 2 * t];
                bh[nt][1] = *(const unsigned*)&bhp[n * SBW + kk + 2 * t + 8];
                bl[nt][0] = *(const unsigned*)&blp[n * SBW + kk + 2 * t];
                bl[nt][1] = *(const unsigned*)&blp[n * SBW + kk + 2 * t + 8];
            }
#pragma unroll
            for (int mt = 0; mt < 4; mt++) {
                int m = wm + mt * 16 + g;
                unsigned ah0 = *(const unsigned*)&sAh[m * SAW + k0 + kk + 2 * t];
                unsigned ah1 = *(const unsigned*)&sAh[(m + 8) * SAW + k0 + kk + 2 * t];
                unsigned ah2 = *(const unsigned*)&sAh[m * SAW + k0 + kk + 2 * t + 8];
                unsigned ah3 = *(const unsigned*)&sAh[(m + 8) * SAW + k0 + kk + 2 * t + 8];
                unsigned al0 = *(const unsigned*)&sAl[m * SAW + k0 + kk + 2 * t];
                unsigned al1 = *(const unsigned*)&sAl[(m + 8) * SAW + k0 + kk + 2 * t];
                unsigned al2 = *(const unsigned*)&sAl[m * SAW + k0 + kk + 2 * t + 8];
                unsigned al3 = *(const unsigned*)&sAl[(m + 8) * SAW + k0 + kk + 2 * t + 8];
#pragma unroll
                for (int nt = 0; nt < NT; nt++) {
                    mma_bf16(acc[mt][nt], ah0, ah1, ah2, ah3, bh[nt][0], bh[nt][1]);
                    mma_bf16(acc[mt][nt], ah0, ah1, ah2, ah3, bl[nt][0], bl[nt][1]);
                    mma_bf16(acc[mt][nt], al0, al1, al2, al3, bh[nt][0], bh[nt][1]);
                }
            }
        }
        if (s < 3) {
            __syncthreads();
            storeB(1 - buf);
            __syncthreads();
        }
    }

    // epilogue: scale by norm, write half messages
#pragma unroll
    for (int mt = 0; mt < 4; mt++) {
        int r0 = m0 + wm + mt * 16 + g, r1 = r0 + 8;
        float n0 = (r0 < NN) ? g_norm[r0] : 0.f;
        float n1 = (r1 < NN) ? g_norm[r1] : 0.f;
#pragma unroll
        for (int nt = 0; nt < NT; nt++) {
            int c = wn + nt * 8 + 2 * t;
            if (r0 < NN) {
                __half2 h = __floats2half2_rn(acc[mt][nt][0] * n0, acc[mt][nt][1] * n0);
                *(__half2*)(Yout + (size_t)r0 * BN + c) = h;
            }
            if (r1 < NN) {
                __half2 h = __floats2half2_rn(acc[mt][nt][2] * n1, acc[mt][nt][3] * n1);
                *(__half2*)(Yout + (size_t)r1 * BN + c) = h;
            }
        }
    }
}

// ---------------- final aggregation (output conv, D=64, no activation) --------
__global__ __launch_bounds__(128) void agg64_kernel(const __half* __restrict__ Yh,
                                                    const float* __restrict__ bias,
                                                    float* __restrict__ outp) {
    int gw = (blockIdx.x * 128 + threadIdx.x) >> 5;
    if (gw >= NN) return;
    int lane = threadIdx.x & 31;
    int beg = g_rowptr[gw], end = g_rowptr[gw + 1];
    float nm = g_norm[gw];
    const int* __restrict__ col = g_col;
    const unsigned* Y2 = (const unsigned*)Yh;
    float2 acc = u2f2(Y2[(size_t)gw * 32 + lane]);
    int e = beg;
    for (; e + 3 < end; e += 4) {
        int s0 = col[e], s1 = col[e + 1], s2 = col[e + 2], s3 = col[e + 3];
        float2 v0 = u2f2(Y2[(size_t)s0 * 32 + lane]);
        float2 v1 = u2f2(Y2[(size_t)s1 * 32 + lane]);
        float2 v2 = u2f2(Y2[(size_t)s2 * 32 + lane]);
        float2 v3 = u2f2(Y2[(size_t)s3 * 32 + lane]);
        acc.x += (v0.x + v1.x) + (v2.x + v3.x);
        acc.y += (v0.y + v1.y) + (v2.y + v3.y);
    }
    for (; e < end; e++) {
        float2 v = u2f2(Y2[(size_t)col[e] * 32 + lane]);
        acc.x += v.x; acc.y += v.y;
    }
    float2 b = ((const float2*)bias)[lane];
    ((float2*)outp)[(size_t)gw * 32 + lane] =
        make_float2(acc.x * nm + b.x, acc.y * nm + b.y);
}

// ---------------- launch ----------------
extern "C" void kernel_launch(void* const* d_in, const int* in_sizes, int n_in,
                              void* d_out, int out_size) {
    const float* inputs = (const float*)d_in[0];
    const int*   edges  = (const int*)d_in[1];
    const float* b_in   = (const float*)d_in[3];
    const float* b1     = (const float*)d_in[5];
    const float* b2     = (const float*)d_in[7];
    const float* b_out  = (const float*)d_in[9];
    float* out = (float*)d_out;

    const int* src = edges;
    const int* dst = edges + NE;

    void *pyA, *pyB, *pxv, *pwh, *pwl, *pcnt;
    cudaGetSymbolAddress(&pyA, g_yA);
    cudaGetSymbolAddress(&pyB, g_yB);
    cudaGetSymbolAddress(&pxv, g_x);
    cudaGetSymbolAddress(&pwh, g_wh);
    cudaGetSymbolAddress(&pwl, g_wl);
    cudaGetSymbolAddress(&pcnt, g_cnt);
    __half* cur = (__half*)pyA;
    __half* nxt = (__half*)pyB;
    float* xv = (float*)pxv;
    __nv_bfloat16* wh = (__nv_bfloat16*)pwh;
    __nv_bfloat16* wl = (__nv_bfloat16*)pwl;

    // dynamic smem sizes for fused kernels
    const int S128 = (2 * 128 * SAW + 4 * 128 * SBW) * 2;  // 110592 B
    const int S64  = (2 * 128 * SAW + 4 * 64 * SBW) * 2;   //  90112 B
    cudaFuncSetAttribute(fused_kernel<128, 0>, cudaFuncAttributeMaxDynamicSharedMemorySize, S128);
    cudaFuncSetAttribute(fused_kernel<128, 1>, cudaFuncAttributeMaxDynamicSharedMemorySize, S128);
    cudaFuncSetAttribute(fused_kernel<128, 2>, cudaFuncAttributeMaxDynamicSharedMemorySize, S128);
    cudaFuncSetAttribute(fused_kernel<64, 3>,  cudaFuncAttributeMaxDynamicSharedMemorySize, S64);

    const int GE = (NE + 255) / 256;
    const int GG = (NN + 127) / 128;       // gemm/fused blocks
    const int GA = (NN * 32 + 127) / 128;  // agg blocks (warp/node)
    const int GW = (NMAT * HD * HD + 255) / 256;
    const size_t WSTEP = (size_t)HD * HD;

    // weight split/transpose + CSR build
    prep_w_kernel<<<GW, 256>>>(inputs ? (const float*)d_in[2] : nullptr,
                               (const float*)d_in[4], (const float*)d_in[6],
                               (const float*)d_in[8]);
    cudaMemsetAsync(pcnt, 0, NN * sizeof(int));
    count_kernel<<<GE, 256>>>(dst);
    scan_blocks_kernel<<<NSB, 1024>>>();
    scan_tops_kernel<<<1, 32>>>();
    scan_fix_kernel<<<NSB, 1024>>>();
    fill_kernel<<<GE, 256>>>(src, dst);

    // conv 0 GEMM: messages from raw inputs
    gemm_tc_kernel<<<GG, 256>>>(inputs, wh, wl, cur);

    // F1: agg(b_in) -> x (leaky, store), gemm W1[0]
    fused_kernel<128, 0><<<GG, 256, S128>>>(cur, b_in, xv, nullptr,
                                            wh + 1 * WSTEP, wl + 1 * WSTEP, nxt);
    { __half* tmp = cur; cur = nxt; nxt = tmp; }

    for (int i = 0; i < 6; i++) {
        // agg(b1[i]) -> h (never stored), gemm W2[i]
        fused_kernel<128, 2><<<GG, 256, S128>>>(cur, b1 + (size_t)i * HD, nullptr, nullptr,
                                                wh + (size_t)(7 + i) * WSTEP,
                                                wl + (size_t)(7 + i) * WSTEP, nxt);
        { __half* tmp = cur; cur = nxt; nxt = tmp; }
        if (i < 5) {
            // agg(b2[i]) residual -> x, gemm W1[i+1]
            fused_kernel<128, 1><<<GG, 256, S128>>>(cur, b2 + (size_t)i * HD, xv, nullptr,
                                                    wh + (size_t)(2 + i) * WSTEP,
                                                    wl + (size_t)(2 + i) * WSTEP, nxt);
        } else {
            // last residual: mirror x into out's second half, gemm W_out (BN=64)
            fused_kernel<64, 3><<<GG, 256, S64>>>(cur, b2 + (size_t)5 * HD, xv,
                                                  out + (size_t)NN * 64,
                                                  wh + (size_t)13 * WSTEP,
                                                  wl + (size_t)13 * WSTEP, nxt);
        }
        { __half* tmp = cur; cur = nxt; nxt = tmp; }
    }

    // final aggregation of output conv -> first N*64 floats of d_out
    agg64_kernel<<<GA, 128>>>(cur, b_out, out);
}

// round 7
// speedup vs baseline: 1.6986x; 1.6986x over previous
#include <cuda_runtime.h>
#include <cuda_fp16.h>
#include <cuda_bf16.h>

#define NN 50000
#define NE 800000
#define HD 128
#define NMAT 14
#define NSB 49   // scan blocks: ceil(50000/1024)

// ---------------- device scratch (no allocations allowed) ----------------
__device__ __half  g_yh[(size_t)NN * HD];   // fp16 messages (GEMM output, norm-scaled)
__device__ __half  g_hh[(size_t)NN * HD];   // fp16 block intermediate h
__device__ float   g_x[(size_t)NN * HD];    // running x (fp32, output)
__device__ float   g_norm[NN];
__device__ int     g_rowptr[NN + 1];
__device__ int     g_cnt[NN];
__device__ int     g_off[NN];
__device__ int     g_col[NE];
__device__ int     g_bsum[NSB];
__device__ __half  g_wh[(size_t)NMAT * HD * HD];  // weights, n-major, fp16 hi
__device__ __half  g_wl[(size_t)NMAT * HD * HD];  // fp16 lo (subnormal-range residual)

__device__ __forceinline__ float lk(float v) { return v >= 0.f ? v : 0.01f * v; }

__device__ __forceinline__ float2 u2f2(unsigned u) {
    __half2 h = *reinterpret_cast<__half2*>(&u);
    return __half22float2(h);
}

// ---------------- CSR build ----------------
__global__ void count_kernel(const int* __restrict__ dst) {
    int e = blockIdx.x * blockDim.x + threadIdx.x;
    if (e < NE) atomicAdd(&g_cnt[dst[e]], 1);
}

__global__ __launch_bounds__(1024) void scan_blocks_kernel() {
    __shared__ int ws[32];
    int tid = threadIdx.x, lane = tid & 31, wid = tid >> 5;
    int i = blockIdx.x * 1024 + tid;
    int v = (i < NN) ? g_cnt[i] : 0;
    int x = v;
#pragma unroll
    for (int d = 1; d < 32; d <<= 1) {
        int t = __shfl_up_sync(0xffffffffu, x, d);
        if (lane >= d) x += t;
    }
    if (lane == 31) ws[wid] = x;
    __syncthreads();
    if (wid == 0) {
        int s = ws[lane];
#pragma unroll
        for (int d = 1; d < 32; d <<= 1) {
            int t = __shfl_up_sync(0xffffffffu, s, d);
            if (lane >= d) s += t;
        }
        ws[lane] = s;
    }
    __syncthreads();
    int off = wid ? ws[wid - 1] : 0;
    if (i < NN) g_rowptr[i] = off + x - v;
    if (tid == 1023) g_bsum[blockIdx.x] = off + x;
}

__global__ void scan_tops_kernel() {
    int lane = threadIdx.x;
    int carry = 0;
    for (int base = 0; base < NSB; base += 32) {
        int i = base + lane;
        int v = (i < NSB) ? g_bsum[i] : 0;
        int x = v;
#pragma unroll
        for (int d = 1; d < 32; d <<= 1) {
            int t = __shfl_up_sync(0xffffffffu, x, d);
            if (lane >= d) x += t;
        }
        if (i < NSB) g_bsum[i] = carry + x - v;
        carry += __shfl_sync(0xffffffffu, x, 31);
    }
    if (lane == 0) g_rowptr[NN] = NE;
}

__global__ __launch_bounds__(1024) void scan_fix_kernel() {
    int i = blockIdx.x * 1024 + threadIdx.x;
    if (i < NN) {
        int r = g_rowptr[i] + g_bsum[blockIdx.x];
        g_rowptr[i] = r;
        g_off[i] = r;
        g_norm[i] = rsqrtf(1.0f + (float)g_cnt[i]);
    }
}

__global__ void fill_kernel(const int* __restrict__ src, const int* __restrict__ dst) {
    int e = blockIdx.x * blockDim.x + threadIdx.x;
    if (e < NE) {
        int d = dst[e];
        int p = atomicAdd(&g_off[d], 1);
        g_col[p] = src[e];
    }
}

// ---------------- weight prep: transpose to n-major, split fp32 -> fp16 hi/lo ----
__global__ void prep_w_kernel(const float* __restrict__ w_in, const float* __restrict__ w1,
                              const float* __restrict__ w2, const float* __restrict__ w_out) {
    int idx = blockIdx.x * blockDim.x + threadIdx.x;
    if (idx >= NMAT * HD * HD) return;
    int mat = idx >> 14;
    int rem = idx & 16383;
    int n = rem >> 7, k = rem & 127;
    float v;
    if (mat == 0)       v = w_in[k * HD + n];
    else if (mat <= 6)  v = w1[(size_t)(mat - 1) * HD * HD + k * HD + n];
    else if (mat <= 12) v = w2[(size_t)(mat - 7) * HD * HD + k * HD + n];
    else                v = (n < 64) ? w_out[k * 64 + n] : 0.f;
    __half hi = __float2half_rn(v);
    __half lo = __float2half_rn(v - __half2float(hi));
    g_wh[idx] = hi;
    g_wl[idx] = lo;
}

// ---------------- fp16 MMA helper (fp32 accumulate) ----------------
__device__ __forceinline__ void mma_f16(float* c, unsigned a0, unsigned a1, unsigned a2,
                                        unsigned a3, unsigned b0, unsigned b1) {
    asm volatile(
        "mma.sync.aligned.m16n8k16.row.col.f32.f16.f16.f32 "
        "{%0,%1,%2,%3}, {%4,%5,%6,%7}, {%8,%9}, {%0,%1,%2,%3};"
        : "+f"(c[0]), "+f"(c[1]), "+f"(c[2]), "+f"(c[3])
        : "r"(a0), "r"(a1), "r"(a2), "r"(a3), "r"(b0), "r"(b1));
}

// ---------------- tensor-core GEMM: Y = half((A@W)*norm), K=128 ----------------
// A fp32 (cvt to fp16) or fp16 direct; W split fp16 hi/lo; 2 MMAs per k16.
// BM=128, BK=32, 256 threads = 8 warps (2 m x 4 n). smem stride 40 halves.
template <int BN, typename AT>
__global__ __launch_bounds__(256) void gemm_tc_kernel(const AT* __restrict__ A,
                                                      const __half* __restrict__ Wh,
                                                      const __half* __restrict__ Wl,
                                                      __half* __restrict__ Yh) {
    constexpr int BM = 128, BK = 32, K = 128;
    constexpr int WN = BN / 4;   // 32 or 16
    constexpr int NT = WN / 8;   // 4 or 2
    constexpr int SA = 40;
    __shared__ __half sA[BM * SA];
    __shared__ __half sBh[BN * SA], sBl[BN * SA];

    const int tid = threadIdx.x, lane = tid & 31, wid = tid >> 5;
    const int g = lane >> 2, t = lane & 3;
    const int wm = (wid & 1) * 64, wn = (wid >> 1) * WN;
    const int m0 = blockIdx.x * BM;

    float acc[4][NT][4];
#pragma unroll
    for (int i = 0; i < 4; i++)
#pragma unroll
        for (int j = 0; j < NT; j++)
#pragma unroll
            for (int q = 0; q < 4; q++) acc[i][j][q] = 0.f;

    float4 vaf[4];
    uint2  vah[4];
    uint4 vbh[2], vbl[2];

    auto loadA = [&](int k0) {
#pragma unroll
        for (int l = 0; l < 4; l++) {
            int idx = tid + l * 256, r = idx >> 3, c = idx & 7;
            if constexpr (sizeof(AT) == 4) {
                vaf[l] = make_float4(0.f, 0.f, 0.f, 0.f);
                if (m0 + r < NN)
                    vaf[l] = *(const float4*)((const float*)A + (size_t)(m0 + r) * K + k0 + c * 4);
            } else {
                vah[l] = make_uint2(0u, 0u);
                if (m0 + r < NN)
                    vah[l] = *(const uint2*)((const __half*)A + (size_t)(m0 + r) * K + k0 + c * 4);
            }
        }
    };
    auto loadB = [&](int k0) {
        if constexpr (BN == 128) {
            int n = tid >> 1, kh = (tid & 1) * 16;
            vbh[0] = *(const uint4*)&Wh[(size_t)n * K + k0 + kh];
            vbh[1] = *(const uint4*)&Wh[(size_t)n * K + k0 + kh + 8];
            vbl[0] = *(const uint4*)&Wl[(size_t)n * K + k0 + kh];
            vbl[1] = *(const uint4*)&Wl[(size_t)n * K + k0 + kh + 8];
        } else {
            int n = tid >> 2, kh = (tid & 3) * 8;
            vbh[0] = *(const uint4*)&Wh[(size_t)n * K + k0 + kh];
            vbl[0] = *(const uint4*)&Wl[(size_t)n * K + k0 + kh];
        }
    };
    auto storeTiles = [&]() {
#pragma unroll
        for (int l = 0; l < 4; l++) {
            int idx = tid + l * 256, r = idx >> 3, c = idx & 7;
            if constexpr (sizeof(AT) == 4) {
                float4 v = vaf[l];
                __half2 h01 = __floats2half2_rn(v.x, v.y);
                __half2 h23 = __floats2half2_rn(v.z, v.w);
                *(__half2*)&sA[r * SA + c * 4]     = h01;
                *(__half2*)&sA[r * SA + c * 4 + 2] = h23;
            } else {
                *(uint2*)&sA[r * SA + c * 4] = vah[l];
            }
        }
        if constexpr (BN == 128) {
            int n = tid >> 1, kh = (tid & 1) * 16;
            *(uint4*)&sBh[n * SA + kh]     = vbh[0];
            *(uint4*)&sBh[n * SA + kh + 8] = vbh[1];
            *(uint4*)&sBl[n * SA + kh]     = vbl[0];
            *(uint4*)&sBl[n * SA + kh + 8] = vbl[1];
        } else {
            int n = tid >> 2, kh = (tid & 3) * 8;
            *(uint4*)&sBh[n * SA + kh] = vbh[0];
            *(uint4*)&sBl[n * SA + kh] = vbl[0];
        }
    };

    loadA(0);
    loadB(0);
    for (int k0 = 0; k0 < K; k0 += BK) {
        storeTiles();
        __syncthreads();
        if (k0 + BK < K) { loadA(k0 + BK); loadB(k0 + BK); }
#pragma unroll
        for (int kk = 0; kk < BK; kk += 16) {
            unsigned bh[NT][2], bl[NT][2];
#pragma unroll
            for (int nt = 0; nt < NT; nt++) {
                int n = wn + nt * 8 + g;
                bh[nt][0] = *(const unsigned*)&sBh[n * SA + kk + 2 * t];
                bh[nt][1] = *(const unsigned*)&sBh[n * SA + kk + 2 * t + 8];
                bl[nt][0] = *(const unsigned*)&sBl[n * SA + kk + 2 * t];
                bl[nt][1] = *(const unsigned*)&sBl[n * SA + kk + 2 * t + 8];
            }
#pragma unroll
            for (int mt = 0; mt < 4; mt++) {
                int m = wm + mt * 16 + g;
                unsigned a0 = *(const unsigned*)&sA[m * SA + kk + 2 * t];
                unsigned a1 = *(const unsigned*)&sA[(m + 8) * SA + kk + 2 * t];
                unsigned a2 = *(const unsigned*)&sA[m * SA + kk + 2 * t + 8];
                unsigned a3 = *(const unsigned*)&sA[(m + 8) * SA + kk + 2 * t + 8];
#pragma unroll
                for (int nt = 0; nt < NT; nt++) {
                    mma_f16(acc[mt][nt], a0, a1, a2, a3, bh[nt][0], bh[nt][1]);
                    mma_f16(acc[mt][nt], a0, a1, a2, a3, bl[nt][0], bl[nt][1]);
                }
            }
        }
        __syncthreads();
    }

#pragma unroll
    for (int mt = 0; mt < 4; mt++) {
        int r0 = m0 + wm + mt * 16 + g, r1 = r0 + 8;
        float n0 = (r0 < NN) ? g_norm[r0] : 0.f;
        float n1 = (r1 < NN) ? g_norm[r1] : 0.f;
#pragma unroll
        for (int nt = 0; nt < NT; nt++) {
            int col = wn + nt * 8 + 2 * t;
            if (r0 < NN) {
                __half2 h = __floats2half2_rn(acc[mt][nt][0] * n0, acc[mt][nt][1] * n0);
                *(__half2*)(Yh + (size_t)r0 * BN + col) = h;
            }
            if (r1 < NN) {
                __half2 h = __floats2half2_rn(acc[mt][nt][2] * n1, acc[mt][nt][3] * n1);
                *(__half2*)(Yh + (size_t)r1 * BN + col) = h;
            }
        }
    }
}

// ---------------- Aggregation: one warp per node, fp16 gather, fp32 accum --------
// out[n] = f( norm[n] * (y[n] + sum_{e: dst=n} y[src_e]) + bias )
// MODE 0: leaky -> OT buffer (float x master, or half h)
// MODE 1: residual (x+leaky)/2 in place (fp32)   MODE 3: MODE 1 + mirror to out2
template <int D, int MODE, typename OT>
__global__ __launch_bounds__(128) void agg_kernel(const __half* __restrict__ Yh,
                                                  const float* __restrict__ bias,
                                                  OT* __restrict__ outp,
                                                  float* __restrict__ out2) {
    int gw = (blockIdx.x * 128 + threadIdx.x) >> 5;
    if (gw >= NN) return;
    int lane = threadIdx.x & 31;
    int beg = g_rowptr[gw], end = g_rowptr[gw + 1];
    float nm = g_norm[gw];
    const int* __restrict__ col = g_col;
    const uint2* Y4 = (const uint2*)Yh;
    uint2 sv = Y4[(size_t)gw * 32 + lane];
    float2 f0 = u2f2(sv.x), f1 = u2f2(sv.y);
    float4 acc = make_float4(f0.x, f0.y, f1.x, f1.y);
    int e = beg;
    for (; e + 3 < end; e += 4) {
        int s0 = col[e], s1 = col[e + 1], s2 = col[e + 2], s3 = col[e + 3];
        uint2 v0 = Y4[(size_t)s0 * 32 + lane];
        uint2 v1 = Y4[(size_t)s1 * 32 + lane];
        uint2 v2 = Y4[(size_t)s2 * 32 + lane];
        uint2 v3 = Y4[(size_t)s3 * 32 + lane];
        float2 a0 = u2f2(v0.x), b0 = u2f2(v0.y);
        float2 a1 = u2f2(v1.x), b1 = u2f2(v1.y);
        float2 a2 = u2f2(v2.x), b2 = u2f2(v2.y);
        float2 a3 = u2f2(v3.x), b3 = u2f2(v3.y);
        acc.x += (a0.x + a1.x) + (a2.x + a3.x);
        acc.y += (a0.y + a1.y) + (a2.y + a3.y);
        acc.z += (b0.x + b1.x) + (b2.x + b3.x);
        acc.w += (b0.y + b1.y) + (b2.y + b3.y);
    }
    for (; e < end; e++) {
        uint2 v = Y4[(size_t)col[e] * 32 + lane];
        float2 a = u2f2(v.x), b = u2f2(v.y);
        acc.x += a.x; acc.y += a.y; acc.z += b.x; acc.w += b.y;
    }
    float4 b = ((const float4*)bias)[lane];
    float4 o = make_float4(acc.x * nm + b.x, acc.y * nm + b.y,
                           acc.z * nm + b.z, acc.w * nm + b.w);
    size_t idx = (size_t)gw * 32 + lane;
    if constexpr (MODE == 0) {
        float4 l4 = make_float4(lk(o.x), lk(o.y), lk(o.z), lk(o.w));
        if constexpr (sizeof(OT) == 4) {
            ((float4*)outp)[idx] = l4;
        } else {
            uint2 p;
            __half2 h01 = __floats2half2_rn(l4.x, l4.y);
            __half2 h23 = __floats2half2_rn(l4.z, l4.w);
            p.x = *reinterpret_cast<unsigned*>(&h01);
            p.y = *reinterpret_cast<unsigned*>(&h23);
            ((uint2*)outp)[idx] = p;
        }
    } else {  // 1 or 3 (OT = float)
        float4 r = ((float4*)outp)[idx];
        float4 nv = make_float4((r.x + lk(o.x)) * 0.5f, (r.y + lk(o.y)) * 0.5f,
                                (r.z + lk(o.z)) * 0.5f, (r.w + lk(o.w)) * 0.5f);
        ((float4*)outp)[idx] = nv;
        if constexpr (MODE == 3) ((float4*)out2)[idx] = nv;
    }
}

// ---------------- final aggregation (output conv, D=64, no activation) --------
__global__ __launch_bounds__(128) void agg64_kernel(const __half* __restrict__ Yh,
                                                    const float* __restrict__ bias,
                                                    float* __restrict__ outp) {
    int gw = (blockIdx.x * 128 + threadIdx.x) >> 5;
    if (gw >= NN) return;
    int lane = threadIdx.x & 31;
    int beg = g_rowptr[gw], end = g_rowptr[gw + 1];
    float nm = g_norm[gw];
    const int* __restrict__ col = g_col;
    const unsigned* Y2 = (const unsigned*)Yh;
    float2 acc = u2f2(Y2[(size_t)gw * 32 + lane]);
    int e = beg;
    for (; e + 3 < end; e += 4) {
        int s0 = col[e], s1 = col[e + 1], s2 = col[e + 2], s3 = col[e + 3];
        float2 v0 = u2f2(Y2[(size_t)s0 * 32 + lane]);
        float2 v1 = u2f2(Y2[(size_t)s1 * 32 + lane]);
        float2 v2 = u2f2(Y2[(size_t)s2 * 32 + lane]);
        float2 v3 = u2f2(Y2[(size_t)s3 * 32 + lane]);
        acc.x += (v0.x + v1.x) + (v2.x + v3.x);
        acc.y += (v0.y + v1.y) + (v2.y + v3.y);
    }
    for (; e < end; e++) {
        float2 v = u2f2(Y2[(size_t)col[e] * 32 + lane]);
        acc.x += v.x; acc.y += v.y;
    }
    float2 b = ((const float2*)bias)[lane];
    ((float2*)outp)[(size_t)gw * 32 + lane] =
        make_float2(acc.x * nm + b.x, acc.y * nm + b.y);
}

// ---------------- launch ----------------
extern "C" void kernel_launch(void* const* d_in, const int* in_sizes, int n_in,
                              void* d_out, int out_size) {
    const float* inputs = (const float*)d_in[0];
    const int*   edges  = (const int*)d_in[1];
    const float* b_in   = (const float*)d_in[3];
    const float* b1     = (const float*)d_in[5];
    const float* b2     = (const float*)d_in[7];
    const float* b_out  = (const float*)d_in[9];
    float* out = (float*)d_out;

    const int* src = edges;
    const int* dst = edges + NE;

    void *pyh, *phh, *pxv, *pwh, *pwl, *pcnt;
    cudaGetSymbolAddress(&pyh, g_yh);
    cudaGetSymbolAddress(&phh, g_hh);
    cudaGetSymbolAddress(&pxv, g_x);
    cudaGetSymbolAddress(&pwh, g_wh);
    cudaGetSymbolAddress(&pwl, g_wl);
    cudaGetSymbolAddress(&pcnt, g_cnt);
    __half* yh = (__half*)pyh;
    __half* hh = (__half*)phh;
    float* xv = (float*)pxv;
    __half* wh = (__half*)pwh;
    __half* wl = (__half*)pwl;

    const int GE = (NE + 255) / 256;
    const int GG = (NN + 127) / 128;       // gemm blocks
    const int GA = (NN * 32 + 127) / 128;  // agg blocks (warp/node, 128-thr blocks)
    const int GW = (NMAT * HD * HD + 255) / 256;
    const size_t WSTEP = (size_t)HD * HD;

    // weight split/transpose + CSR build
    prep_w_kernel<<<GW, 256>>>((const float*)d_in[2], (const float*)d_in[4],
                               (const float*)d_in[6], (const float*)d_in[8]);
    cudaMemsetAsync(pcnt, 0, NN * sizeof(int));
    count_kernel<<<GE, 256>>>(dst);
    scan_blocks_kernel<<<NSB, 1024>>>();
    scan_tops_kernel<<<1, 32>>>();
    scan_fix_kernel<<<NSB, 1024>>>();
    fill_kernel<<<GE, 256>>>(src, dst);

    // input conv
    gemm_tc_kernel<128, float><<<GG, 256>>>(inputs, wh, wl, yh);
    agg_kernel<128, 0, float><<<GA, 128>>>(yh, b_in, xv, nullptr);

    // 6 residual blocks; last one mirrors x into d_out's second half
    for (int i = 0; i < 6; i++) {
        gemm_tc_kernel<128, float><<<GG, 256>>>(xv, wh + (size_t)(1 + i) * WSTEP,
                                                wl + (size_t)(1 + i) * WSTEP, yh);
        agg_kernel<128, 0, __half><<<GA, 128>>>(yh, b1 + (size_t)i * HD, hh, nullptr);
        gemm_tc_kernel<128, __half><<<GG, 256>>>(hh, wh + (size_t)(7 + i) * WSTEP,
                                                 wl + (size_t)(7 + i) * WSTEP, yh);
        if (i < 5)
            agg_kernel<128, 1, float><<<GA, 128>>>(yh, b2 + (size_t)i * HD, xv, nullptr);
        else
            agg_kernel<128, 3, float><<<GA, 128>>>(yh, b2 + (size_t)i * HD, xv,
                                                   out + (size_t)NN * 64);
    }

    // output conv (no activation), writes first N*64 floats of d_out
    gemm_tc_kernel<64, float><<<GG, 256>>>(xv, wh + (size_t)13 * WSTEP,
                                           wl + (size_t)13 * WSTEP, yh);
    agg64_kernel<<<GA, 128>>>(yh, b_out, out);
}

// round 9
// speedup vs baseline: 1.7220x; 1.0138x over previous
#include <cuda_runtime.h>
#include <cuda_fp16.h>
#include <cuda_bf16.h>

#define NN 50000
#define NE 800000
#define HD 128
#define NMAT 14
#define NSB 49   // scan blocks: ceil(50000/1024)

// ---------------- device scratch (no allocations allowed) ----------------
__device__ __half  g_yh[(size_t)NN * HD];   // fp16 messages (GEMM output, norm-scaled)
__device__ __half  g_hh[(size_t)NN * HD];   // fp16 block intermediate h
__device__ __half  g_xh[(size_t)NN * HD];   // fp16 running x master
__device__ float   g_norm[NN];
__device__ int     g_rowptr[NN + 1];
__device__ int     g_cnt[NN];
__device__ int     g_off[NN];
__device__ int     g_col[NE];
__device__ int     g_bsum[NSB];             // raw per-block totals
__device__ __half  g_wh[(size_t)NMAT * HD * HD];  // weights, n-major, fp16 hi
__device__ __half  g_wl[(size_t)NMAT * HD * HD];  // fp16 lo residual

__device__ __forceinline__ float lk(float v) { return v >= 0.f ? v : 0.01f * v; }

__device__ __forceinline__ float2 u2f2(unsigned u) {
    __half2 h = *reinterpret_cast<__half2*>(&u);
    return __half22float2(h);
}

// ---------------- CSR build ----------------
__global__ void count_kernel(const int* __restrict__ dst) {
    int e = blockIdx.x * blockDim.x + threadIdx.x;
    if (e < NE) atomicAdd(&g_cnt[dst[e]], 1);
}

// per-block exclusive scan of g_cnt -> g_rowptr (block-local), raw totals -> g_bsum
__global__ __launch_bounds__(1024) void scan_blocks_kernel() {
    __shared__ int ws[32];
    int tid = threadIdx.x, lane = tid & 31, wid = tid >> 5;
    int i = blockIdx.x * 1024 + tid;
    int v = (i < NN) ? g_cnt[i] : 0;
    int x = v;
#pragma unroll
    for (int d = 1; d < 32; d <<= 1) {
        int t = __shfl_up_sync(0xffffffffu, x, d);
        if (lane >= d) x += t;
    }
    if (lane == 31) ws[wid] = x;
    __syncthreads();
    if (wid == 0) {
        int s = ws[lane];
#pragma unroll
        for (int d = 1; d < 32; d <<= 1) {
            int t = __shfl_up_sync(0xffffffffu, s, d);
            if (lane >= d) s += t;
        }
        ws[lane] = s;
    }
    __syncthreads();
    int off = wid ? ws[wid - 1] : 0;
    if (i < NN) g_rowptr[i] = off + x - v;
    if (tid == 1023) g_bsum[blockIdx.x] = off + x;
}

// add global block offsets (masked warp reduce over raw totals), init off + norm
__global__ __launch_bounds__(1024) void scan_fix_kernel() {
    __shared__ int s_off;
    int tid = threadIdx.x;
    if (tid < 32) {
        int b = blockIdx.x;
        int t0 = (tid < NSB && tid < b) ? g_bsum[tid] : 0;
        int t1 = (tid + 32 < NSB && tid + 32 < b) ? g_bsum[tid + 32] : 0;
        int s = t0 + t1;
#pragma unroll
        for (int d = 16; d >= 1; d >>= 1) s += __shfl_xor_sync(0xffffffffu, s, d);
        if (tid == 0) s_off = s;
    }
    __syncthreads();
    int i = blockIdx.x * 1024 + tid;
    if (i < NN) {
        int r = g_rowptr[i] + s_off;
        g_rowptr[i] = r;
        g_off[i] = r;
        g_norm[i] = rsqrtf(1.0f + (float)g_cnt[i]);
    }
    if (blockIdx.x == 0 && tid == 0) g_rowptr[NN] = NE;
}

__global__ void fill_kernel(const int* __restrict__ src, const int* __restrict__ dst) {
    int e = blockIdx.x * blockDim.x + threadIdx.x;
    if (e < NE) {
        int d = dst[e];
        int p = atomicAdd(&g_off[d], 1);
        g_col[p] = src[e];
    }
}

// ---------------- weight prep: transpose to n-major, split fp32 -> fp16 hi/lo ----
__global__ void prep_w_kernel(const float* __restrict__ w_in, const float* __restrict__ w1,
                              const float* __restrict__ w2, const float* __restrict__ w_out) {
    int idx = blockIdx.x * blockDim.x + threadIdx.x;
    if (idx >= NMAT * HD * HD) return;
    int mat = idx >> 14;
    int rem = idx & 16383;
    int n = rem >> 7, k = rem & 127;
    float v;
    if (mat == 0)       v = w_in[k * HD + n];
    else if (mat <= 6)  v = w1[(size_t)(mat - 1) * HD * HD + k * HD + n];
    else if (mat <= 12) v = w2[(size_t)(mat - 7) * HD * HD + k * HD + n];
    else                v = (n < 64) ? w_out[k * 64 + n] : 0.f;
    __half hi = __float2half_rn(v);
    __half lo = __float2half_rn(v - __half2float(hi));
    g_wh[idx] = hi;
    g_wl[idx] = lo;
}

// ---------------- fp16 MMA helper (fp32 accumulate) ----------------
__device__ __forceinline__ void mma_f16(float* c, unsigned a0, unsigned a1, unsigned a2,
                                        unsigned a3, unsigned b0, unsigned b1) {
    asm volatile(
        "mma.sync.aligned.m16n8k16.row.col.f32.f16.f16.f32 "
        "{%0,%1,%2,%3}, {%4,%5,%6,%7}, {%8,%9}, {%0,%1,%2,%3};"
        : "+f"(c[0]), "+f"(c[1]), "+f"(c[2]), "+f"(c[3])
        : "r"(a0), "r"(a1), "r"(a2), "r"(a3), "r"(b0), "r"(b1));
}

// ---------------- tensor-core GEMM: Y = half((A@W)*norm), K=128 ----------------
// A fp32 (cvt to fp16) or fp16 direct; W split fp16 hi/lo; 2 MMAs per k16.
template <int BN, typename AT>
__global__ __launch_bounds__(256) void gemm_tc_kernel(const AT* __restrict__ A,
                                                      const __half* __restrict__ Wh,
                                                      const __half* __restrict__ Wl,
                                                      __half* __restrict__ Yh) {
    constexpr int BM = 128, BK = 32, K = 128;
    constexpr int WN = BN / 4;   // 32 or 16
    constexpr int NT = WN / 8;   // 4 or 2
    constexpr int SA = 40;
    __shared__ __half sA[BM * SA];
    __shared__ __half sBh[BN * SA], sBl[BN * SA];

    const int tid = threadIdx.x, lane = tid & 31, wid = tid >> 5;
    const int g = lane >> 2, t = lane & 3;
    const int wm = (wid & 1) * 64, wn = (wid >> 1) * WN;
    const int m0 = blockIdx.x * BM;

    float acc[4][NT][4];
#pragma unroll
    for (int i = 0; i < 4; i++)
#pragma unroll
        for (int j = 0; j < NT; j++)
#pragma unroll
            for (int q = 0; q < 4; q++) acc[i][j][q] = 0.f;

    float4 vaf[4];
    uint2  vah[4];
    uint4 vbh[2], vbl[2];

    auto loadA = [&](int k0) {
#pragma unroll
        for (int l = 0; l < 4; l++) {
            int idx = tid + l * 256, r = idx >> 3, c = idx & 7;
            if constexpr (sizeof(AT) == 4) {
                vaf[l] = make_float4(0.f, 0.f, 0.f, 0.f);
                if (m0 + r < NN)
                    vaf[l] = *(const float4*)((const float*)A + (size_t)(m0 + r) * K + k0 + c * 4);
            } else {
                vah[l] = make_uint2(0u, 0u);
                if (m0 + r < NN)
                    vah[l] = *(const uint2*)((const __half*)A + (size_t)(m0 + r) * K + k0 + c * 4);
            }
        }
    };
    auto loadB = [&](int k0) {
        if constexpr (BN == 128) {
            int n = tid >> 1, kh = (tid & 1) * 16;
            vbh[0] = *(const uint4*)&Wh[(size_t)n * K + k0 + kh];
            vbh[1] = *(const uint4*)&Wh[(size_t)n * K + k0 + kh + 8];
            vbl[0] = *(const uint4*)&Wl[(size_t)n * K + k0 + kh];
            vbl[1] = *(const uint4*)&Wl[(size_t)n * K + k0 + kh + 8];
        } else {
            int n = tid >> 2, kh = (tid & 3) * 8;
            vbh[0] = *(const uint4*)&Wh[(size_t)n * K + k0 + kh];
            vbl[0] = *(const uint4*)&Wl[(size_t)n * K + k0 + kh];
        }
    };
    auto storeTiles = [&]() {
#pragma unroll
        for (int l = 0; l < 4; l++) {
            int idx = tid + l * 256, r = idx >> 3, c = idx & 7;
            if constexpr (sizeof(AT) == 4) {
                float4 v = vaf[l];
                __half2 h01 = __floats2half2_rn(v.x, v.y);
                __half2 h23 = __floats2half2_rn(v.z, v.w);
                *(__half2*)&sA[r * SA + c * 4]     = h01;
                *(__half2*)&sA[r * SA + c * 4 + 2] = h23;
            } else {
                *(uint2*)&sA[r * SA + c * 4] = vah[l];
            }
        }
        if constexpr (BN == 128) {
            int n = tid >> 1, kh = (tid & 1) * 16;
            *(uint4*)&sBh[n * SA + kh]     = vbh[0];
            *(uint4*)&sBh[n * SA + kh + 8] = vbh[1];
            *(uint4*)&sBl[n * SA + kh]     = vbl[0];
            *(uint4*)&sBl[n * SA + kh + 8] = vbl[1];
        } else {
            int n = tid >> 2, kh = (tid & 3) * 8;
            *(uint4*)&sBh[n * SA + kh] = vbh[0];
            *(uint4*)&sBl[n * SA + kh] = vbl[0];
        }
    };

    loadA(0);
    loadB(0);
    for (int k0 = 0; k0 < K; k0 += BK) {
        storeTiles();
        __syncthreads();
        if (k0 + BK < K) { loadA(k0 + BK); loadB(k0 + BK); }
#pragma unroll
        for (int kk = 0; kk < BK; kk += 16) {
            unsigned bh[NT][2], bl[NT][2];
#pragma unroll
            for (int nt = 0; nt < NT; nt++) {
                int n = wn + nt * 8 + g;
                bh[nt][0] = *(const unsigned*)&sBh[n * SA + kk + 2 * t];
                bh[nt][1] = *(const unsigned*)&sBh[n * SA + kk + 2 * t + 8];
                bl[nt][0] = *(const unsigned*)&sBl[n * SA + kk + 2 * t];
                bl[nt][1] = *(const unsigned*)&sBl[n * SA + kk + 2 * t + 8];
            }
#pragma unroll
            for (int mt = 0; mt < 4; mt++) {
                int m = wm + mt * 16 + g;
                unsigned a0 = *(const unsigned*)&sA[m * SA + kk + 2 * t];
                unsigned a1 = *(const unsigned*)&sA[(m + 8) * SA + kk + 2 * t];
                unsigned a2 = *(const unsigned*)&sA[m * SA + kk + 2 * t + 8];
                unsigned a3 = *(const unsigned*)&sA[(m + 8) * SA + kk + 2 * t + 8];
#pragma unroll
                for (int nt = 0; nt < NT; nt++) {
                    mma_f16(acc[mt][nt], a0, a1, a2, a3, bh[nt][0], bh[nt][1]);
                    mma_f16(acc[mt][nt], a0, a1, a2, a3, bl[nt][0], bl[nt][1]);
                }
            }
        }
        __syncthreads();
    }

#pragma unroll
    for (int mt = 0; mt < 4; mt++) {
        int r0 = m0 + wm + mt * 16 + g, r1 = r0 + 8;
        float n0 = (r0 < NN) ? g_norm[r0] : 0.f;
        float n1 = (r1 < NN) ? g_norm[r1] : 0.f;
#pragma unroll
        for (int nt = 0; nt < NT; nt++) {
            int col = wn + nt * 8 + 2 * t;
            if (r0 < NN) {
                __half2 h = __floats2half2_rn(acc[mt][nt][0] * n0, acc[mt][nt][1] * n0);
                *(__half2*)(Yh + (size_t)r0 * BN + col) = h;
            }
            if (r1 < NN) {
                __half2 h = __floats2half2_rn(acc[mt][nt][2] * n1, acc[mt][nt][3] * n1);
                *(__half2*)(Yh + (size_t)r1 * BN + col) = h;
            }
        }
    }
}

// ---------------- Aggregation: one warp per node, fp16 gather + fp16 state ------
// o = norm[n]*(y[n] + sum y[src]) + bias
// MODE 0: leaky(o) -> half buffer (x init or h)
// MODE 1: x = (x + leaky(o))*0.5, fp16 master in place
// MODE 3: MODE 1 + unrounded fp32 mirror to out2
template <int MODE>
__global__ __launch_bounds__(128) void agg_kernel(const __half* __restrict__ Yh,
                                                  const float* __restrict__ bias,
                                                  __half* __restrict__ xbuf,
                                                  float* __restrict__ out2) {
    int gw = (blockIdx.x * 128 + threadIdx.x) >> 5;
    if (gw >= NN) return;
    int lane = threadIdx.x & 31;
    int beg = g_rowptr[gw], end = g_rowptr[gw + 1];
    float nm = g_norm[gw];
    const int* __restrict__ col = g_col;
    const uint2* Y4 = (const uint2*)Yh;
    uint2 sv = Y4[(size_t)gw * 32 + lane];
    float2 f0 = u2f2(sv.x), f1 = u2f2(sv.y);
    float4 acc = make_float4(f0.x, f0.y, f1.x, f1.y);
    int e = beg;
    for (; e + 3 < end; e += 4) {
        int s0 = col[e], s1 = col[e + 1], s2 = col[e + 2], s3 = col[e + 3];
        uint2 v0 = Y4[(size_t)s0 * 32 + lane];
        uint2 v1 = Y4[(size_t)s1 * 32 + lane];
        uint2 v2 = Y4[(size_t)s2 * 32 + lane];
        uint2 v3 = Y4[(size_t)s3 * 32 + lane];
        float2 a0 = u2f2(v0.x), b0 = u2f2(v0.y);
        float2 a1 = u2f2(v1.x), b1 = u2f2(v1.y);
        float2 a2 = u2f2(v2.x), b2 = u2f2(v2.y);
        float2 a3 = u2f2(v3.x), b3 = u2f2(v3.y);
        acc.x += (a0.x + a1.x) + (a2.x + a3.x);
        acc.y += (a0.y + a1.y) + (a2.y + a3.y);
        acc.z += (b0.x + b1.x) + (b2.x + b3.x);
        acc.w += (b0.y + b1.y) + (b2.y + b3.y);
    }
    for (; e < end; e++) {
        uint2 v = Y4[(size_t)col[e] * 32 + lane];
        float2 a = u2f2(v.x), b = u2f2(v.y);
        acc.x += a.x; acc.y += a.y; acc.z += b.x; acc.w += b.y;
    }
    float4 b = ((const float4*)bias)[lane];
    float4 o = make_float4(acc.x * nm + b.x, acc.y * nm + b.y,
                           acc.z * nm + b.z, acc.w * nm + b.w);
    size_t idx = (size_t)gw * 32 + lane;
    float4 l4 = make_float4(lk(o.x), lk(o.y), lk(o.z), lk(o.w));
    float4 nv;
    if constexpr (MODE == 0) {
        nv = l4;
    } else {
        uint2 xr = ((const uint2*)xbuf)[idx];
        float2 x0 = u2f2(xr.x), x1 = u2f2(xr.y);
        nv = make_float4((x0.x + l4.x) * 0.5f, (x0.y + l4.y) * 0.5f,
                         (x1.x + l4.z) * 0.5f, (x1.y + l4.w) * 0.5f);
        if constexpr (MODE == 3) ((float4*)out2)[idx] = nv;
    }
    uint2 p;
    __half2 h01 = __floats2half2_rn(nv.x, nv.y);
    __half2 h23 = __floats2half2_rn(nv.z, nv.w);
    p.x = *reinterpret_cast<unsigned*>(&h01);
    p.y = *reinterpret_cast<unsigned*>(&h23);
    ((uint2*)xbuf)[idx] = p;
}

// ---------------- final aggregation (output conv, D=64, no activation) --------
__global__ __launch_bounds__(128) void agg64_kernel(const __half* __restrict__ Yh,
                                                    const float* __restrict__ bias,
                                                    float* __restrict__ outp) {
    int gw = (blockIdx.x * 128 + threadIdx.x) >> 5;
    if (gw >= NN) return;
    int lane = threadIdx.x & 31;
    int beg = g_rowptr[gw], end = g_rowptr[gw + 1];
    float nm = g_norm[gw];
    const int* __restrict__ col = g_col;
    const unsigned* Y2 = (const unsigned*)Yh;
    float2 acc = u2f2(Y2[(size_t)gw * 32 + lane]);
    int e = beg;
    for (; e + 3 < end; e += 4) {
        int s0 = col[e], s1 = col[e + 1], s2 = col[e + 2], s3 = col[e + 3];
        float2 v0 = u2f2(Y2[(size_t)s0 * 32 + lane]);
        float2 v1 = u2f2(Y2[(size_t)s1 * 32 + lane]);
        float2 v2 = u2f2(Y2[(size_t)s2 * 32 + lane]);
        float2 v3 = u2f2(Y2[(size_t)s3 * 32 + lane]);
        acc.x += (v0.x + v1.x) + (v2.x + v3.x);
        acc.y += (v0.y + v1.y) + (v2.y + v3.y);
    }
    for (; e < end; e++) {
        float2 v = u2f2(Y2[(size_t)col[e] * 32 + lane]);
        acc.x += v.x; acc.y += v.y;
    }
    float2 b = ((const float2*)bias)[lane];
    ((float2*)outp)[(size_t)gw * 32 + lane] =
        make_float2(acc.x * nm + b.x, acc.y * nm + b.y);
}

// ---------------- launch ----------------
extern "C" void kernel_launch(void* const* d_in, const int* in_sizes, int n_in,
                              void* d_out, int out_size) {
    const float* inputs = (const float*)d_in[0];
    const int*   edges  = (const int*)d_in[1];
    const float* b_in   = (const float*)d_in[3];
    const float* b1     = (const float*)d_in[5];
    const float* b2     = (const float*)d_in[7];
    const float* b_out  = (const float*)d_in[9];
    float* out = (float*)d_out;

    const int* src = edges;
    const int* dst = edges + NE;

    void *pyh, *phh, *pxh, *pwh, *pwl, *pcnt;
    cudaGetSymbolAddress(&pyh, g_yh);
    cudaGetSymbolAddress(&phh, g_hh);
    cudaGetSymbolAddress(&pxh, g_xh);
    cudaGetSymbolAddress(&pwh, g_wh);
    cudaGetSymbolAddress(&pwl, g_wl);
    cudaGetSymbolAddress(&pcnt, g_cnt);
    __half* yh = (__half*)pyh;
    __half* hh = (__half*)phh;
    __half* xh = (__half*)pxh;
    __half* wh = (__half*)pwh;
    __half* wl = (__half*)pwl;

    const int GE = (NE + 255) / 256;
    const int GG = (NN + 127) / 128;       // gemm blocks
    const int GA = (NN * 32 + 127) / 128;  // agg blocks (warp/node, 128-thr blocks)
    const int GW = (NMAT * HD * HD + 255) / 256;
    const size_t WSTEP = (size_t)HD * HD;

    // weight split/transpose + CSR build
    prep_w_kernel<<<GW, 256>>>((const float*)d_in[2], (const float*)d_in[4],
                               (const float*)d_in[6], (const float*)d_in[8]);
    cudaMemsetAsync(pcnt, 0, NN * sizeof(int));
    count_kernel<<<GE, 256>>>(dst);
    scan_blocks_kernel<<<NSB, 1024>>>();
    scan_fix_kernel<<<NSB, 1024>>>();
    fill_kernel<<<GE, 256>>>(src, dst);

    // input conv
    gemm_tc_kernel<128, float><<<GG, 256>>>(inputs, wh, wl, yh);
    agg_kernel<0><<<GA, 128>>>(yh, b_in, xh, nullptr);

    // 6 residual blocks; last one mirrors fp32 x into d_out's second half
    for (int i = 0; i < 6; i++) {
        gemm_tc_kernel<128, __half><<<GG, 256>>>(xh, wh + (size_t)(1 + i) * WSTEP,
                                                 wl + (size_t)(1 + i) * WSTEP, yh);
        agg_kernel<0><<<GA, 128>>>(yh, b1 + (size_t)i * HD, hh, nullptr);
        gemm_tc_kernel<128, __half><<<GG, 256>>>(hh, wh + (size_t)(7 + i) * WSTEP,
                                                 wl + (size_t)(7 + i) * WSTEP, yh);
        if (i < 5)
            agg_kernel<1><<<GA, 128>>>(yh, b2 + (size_t)i * HD, xh, nullptr);
        else
            agg_kernel<3><<<GA, 128>>>(yh, b2 + (size_t)i * HD, xh,
                                       out + (size_t)NN * 64);
    }

    // output conv (no activation), writes first N*64 floats of d_out
    gemm_tc_kernel<64, __half><<<GG, 256>>>(xh, wh + (size_t)13 * WSTEP,
                                            wl + (size_t)13 * WSTEP, yh);
    agg64_kernel<<<GA, 128>>>(yh, b_out, out);
}

// round 10
// speedup vs baseline: 1.7997x; 1.0451x over previous
#include <cuda_runtime.h>
#include <cuda_fp16.h>
#include <cuda_bf16.h>

#define NN 50000
#define NE 800000
#define HD 128
#define NMAT 14
#define NSB 49   // scan blocks: ceil(50000/1024)

// ---------------- device scratch (no allocations allowed) ----------------
__device__ __half  g_yh[(size_t)NN * HD];   // fp16 messages (GEMM output, norm-scaled)
__device__ __half  g_hh[(size_t)NN * HD];   // fp16 block intermediate h
__device__ __half  g_xh[(size_t)NN * HD];   // fp16 running x master
__device__ float   g_norm[NN];
__device__ int     g_rowptr[NN + 1];
__device__ int     g_cnt[NN];
__device__ int     g_off[NN];
__device__ int     g_col[NE];
__device__ int     g_bsum[NSB];             // raw per-block totals
__device__ __half  g_wh[(size_t)NMAT * HD * HD];  // weights, n-major, fp16 hi
__device__ __half  g_wl[(size_t)NMAT * HD * HD];  // fp16 lo residual

__device__ __forceinline__ float lk(float v) { return v >= 0.f ? v : 0.01f * v; }

__device__ __forceinline__ float2 u2f2(unsigned u) {
    __half2 h = *reinterpret_cast<__half2*>(&u);
    return __half22float2(h);
}

// ---------------- CSR build ----------------
__global__ void count_kernel(const int* __restrict__ dst) {
    int e = blockIdx.x * blockDim.x + threadIdx.x;
    if (e < NE) atomicAdd(&g_cnt[dst[e]], 1);
}

__global__ __launch_bounds__(1024) void scan_blocks_kernel() {
    __shared__ int ws[32];
    int tid = threadIdx.x, lane = tid & 31, wid = tid >> 5;
    int i = blockIdx.x * 1024 + tid;
    int v = (i < NN) ? g_cnt[i] : 0;
    int x = v;
#pragma unroll
    for (int d = 1; d < 32; d <<= 1) {
        int t = __shfl_up_sync(0xffffffffu, x, d);
        if (lane >= d) x += t;
    }
    if (lane == 31) ws[wid] = x;
    __syncthreads();
    if (wid == 0) {
        int s = ws[lane];
#pragma unroll
        for (int d = 1; d < 32; d <<= 1) {
            int t = __shfl_up_sync(0xffffffffu, s, d);
            if (lane >= d) s += t;
        }
        ws[lane] = s;
    }
    __syncthreads();
    int off = wid ? ws[wid - 1] : 0;
    if (i < NN) g_rowptr[i] = off + x - v;
    if (tid == 1023) g_bsum[blockIdx.x] = off + x;
}

__global__ __launch_bounds__(1024) void scan_fix_kernel() {
    __shared__ int s_off;
    int tid = threadIdx.x;
    if (tid < 32) {
        int b = blockIdx.x;
        int t0 = (tid < NSB && tid < b) ? g_bsum[tid] : 0;
        int t1 = (tid + 32 < NSB && tid + 32 < b) ? g_bsum[tid + 32] : 0;
        int s = t0 + t1;
#pragma unroll
        for (int d = 16; d >= 1; d >>= 1) s += __shfl_xor_sync(0xffffffffu, s, d);
        if (tid == 0) s_off = s;
    }
    __syncthreads();
    int i = blockIdx.x * 1024 + tid;
    if (i < NN) {
        int r = g_rowptr[i] + s_off;
        g_rowptr[i] = r;
        g_off[i] = r;
        g_norm[i] = rsqrtf(1.0f + (float)g_cnt[i]);
    }
    if (blockIdx.x == 0 && tid == 0) g_rowptr[NN] = NE;
}

__global__ void fill_kernel(const int* __restrict__ src, const int* __restrict__ dst) {
    int e = blockIdx.x * blockDim.x + threadIdx.x;
    if (e < NE) {
        int d = dst[e];
        int p = atomicAdd(&g_off[d], 1);
        g_col[p] = src[e];
    }
}

// ---------------- weight prep: transpose to n-major, split fp32 -> fp16 hi/lo ----
__global__ void prep_w_kernel(const float* __restrict__ w_in, const float* __restrict__ w1,
                              const float* __restrict__ w2, const float* __restrict__ w_out) {
    int idx = blockIdx.x * blockDim.x + threadIdx.x;
    if (idx >= NMAT * HD * HD) return;
    int mat = idx >> 14;
    int rem = idx & 16383;
    int n = rem >> 7, k = rem & 127;
    float v;
    if (mat == 0)       v = w_in[k * HD + n];
    else if (mat <= 6)  v = w1[(size_t)(mat - 1) * HD * HD + k * HD + n];
    else if (mat <= 12) v = w2[(size_t)(mat - 7) * HD * HD + k * HD + n];
    else                v = (n < 64) ? w_out[k * 64 + n] : 0.f;
    __half hi = __float2half_rn(v);
    __half lo = __float2half_rn(v - __half2float(hi));
    g_wh[idx] = hi;
    g_wl[idx] = lo;
}

// ---------------- fp16 MMA helper (fp32 accumulate) ----------------
__device__ __forceinline__ void mma_f16(float* c, unsigned a0, unsigned a1, unsigned a2,
                                        unsigned a3, unsigned b0, unsigned b1) {
    asm volatile(
        "mma.sync.aligned.m16n8k16.row.col.f32.f16.f16.f32 "
        "{%0,%1,%2,%3}, {%4,%5,%6,%7}, {%8,%9}, {%0,%1,%2,%3};"
        : "+f"(c[0]), "+f"(c[1]), "+f"(c[2]), "+f"(c[3])
        : "r"(a0), "r"(a1), "r"(a2), "r"(a3), "r"(b0), "r"(b1));
}

// ---------------- tensor-core GEMM, double-buffered smem (1 sync/stage) --------
// Y = half((A@W)*norm), K=128. A fp32->fp16 or fp16; W split fp16 hi/lo.
template <int BN, typename AT>
__global__ __launch_bounds__(256) void gemm_tc_kernel(const AT* __restrict__ A,
                                                      const __half* __restrict__ Wh,
                                                      const __half* __restrict__ Wl,
                                                      __half* __restrict__ Yh) {
    constexpr int BM = 128, BK = 32, K = 128;
    constexpr int WN = BN / 4;   // 32 or 16
    constexpr int NT = WN / 8;   // 4 or 2
    constexpr int SA = 40;
    constexpr int ASZ = BM * SA;       // per-buffer A halves
    constexpr int BSZ = BN * SA;       // per-buffer B halves
    extern __shared__ __half smem[];
    __half* sA  = smem;                // 2 * ASZ
    __half* sBh = smem + 2 * ASZ;      // 2 * BSZ
    __half* sBl = sBh + 2 * BSZ;       // 2 * BSZ

    const int tid = threadIdx.x, lane = tid & 31, wid = tid >> 5;
    const int g = lane >> 2, t = lane & 3;
    const int wm = (wid & 1) * 64, wn = (wid >> 1) * WN;
    const int m0 = blockIdx.x * BM;

    float acc[4][NT][4];
#pragma unroll
    for (int i = 0; i < 4; i++)
#pragma unroll
        for (int j = 0; j < NT; j++)
#pragma unroll
            for (int q = 0; q < 4; q++) acc[i][j][q] = 0.f;

    float4 vaf[4];
    uint2  vah[4];
    uint4 vbh[2], vbl[2];

    auto loadA = [&](int k0) {
#pragma unroll
        for (int l = 0; l < 4; l++) {
            int idx = tid + l * 256, r = idx >> 3, c = idx & 7;
            if constexpr (sizeof(AT) == 4) {
                vaf[l] = make_float4(0.f, 0.f, 0.f, 0.f);
                if (m0 + r < NN)
                    vaf[l] = *(const float4*)((const float*)A + (size_t)(m0 + r) * K + k0 + c * 4);
            } else {
                vah[l] = make_uint2(0u, 0u);
                if (m0 + r < NN)
                    vah[l] = *(const uint2*)((const __half*)A + (size_t)(m0 + r) * K + k0 + c * 4);
            }
        }
    };
    auto loadB = [&](int k0) {
        if constexpr (BN == 128) {
            int n = tid >> 1, kh = (tid & 1) * 16;
            vbh[0] = *(const uint4*)&Wh[(size_t)n * K + k0 + kh];
            vbh[1] = *(const uint4*)&Wh[(size_t)n * K + k0 + kh + 8];
            vbl[0] = *(const uint4*)&Wl[(size_t)n * K + k0 + kh];
            vbl[1] = *(const uint4*)&Wl[(size_t)n * K + k0 + kh + 8];
        } else {
            int n = tid >> 2, kh = (tid & 3) * 8;
            vbh[0] = *(const uint4*)&Wh[(size_t)n * K + k0 + kh];
            vbl[0] = *(const uint4*)&Wl[(size_t)n * K + k0 + kh];
        }
    };
    auto storeTiles = [&](int buf) {
        __half* dA  = sA  + buf * ASZ;
        __half* dBh = sBh + buf * BSZ;
        __half* dBl = sBl + buf * BSZ;
#pragma unroll
        for (int l = 0; l < 4; l++) {
            int idx = tid + l * 256, r = idx >> 3, c = idx & 7;
            if constexpr (sizeof(AT) == 4) {
                float4 v = vaf[l];
                __half2 h01 = __floats2half2_rn(v.x, v.y);
                __half2 h23 = __floats2half2_rn(v.z, v.w);
                *(__half2*)&dA[r * SA + c * 4]     = h01;
                *(__half2*)&dA[r * SA + c * 4 + 2] = h23;
            } else {
                *(uint2*)&dA[r * SA + c * 4] = vah[l];
            }
        }
        if constexpr (BN == 128) {
            int n = tid >> 1, kh = (tid & 1) * 16;
            *(uint4*)&dBh[n * SA + kh]     = vbh[0];
            *(uint4*)&dBh[n * SA + kh + 8] = vbh[1];
            *(uint4*)&dBl[n * SA + kh]     = vbl[0];
            *(uint4*)&dBl[n * SA + kh + 8] = vbl[1];
        } else {
            int n = tid >> 2, kh = (tid & 3) * 8;
            *(uint4*)&dBh[n * SA + kh] = vbh[0];
            *(uint4*)&dBl[n * SA + kh] = vbl[0];
        }
    };

    loadA(0);
    loadB(0);
    storeTiles(0);
    __syncthreads();
#pragma unroll
    for (int s = 0; s < 4; s++) {
        if (s < 3) { loadA((s + 1) * BK); loadB((s + 1) * BK); }
        const int buf = s & 1;
        const __half* cA  = sA  + buf * ASZ;
        const __half* cBh = sBh + buf * BSZ;
        const __half* cBl = sBl + buf * BSZ;
#pragma unroll
        for (int kk = 0; kk < BK; kk += 16) {
            unsigned bh[NT][2], bl[NT][2];
#pragma unroll
            for (int nt = 0; nt < NT; nt++) {
                int n = wn + nt * 8 + g;
                bh[nt][0] = *(const unsigned*)&cBh[n * SA + kk + 2 * t];
                bh[nt][1] = *(const unsigned*)&cBh[n * SA + kk + 2 * t + 8];
                bl[nt][0] = *(const unsigned*)&cBl[n * SA + kk + 2 * t];
                bl[nt][1] = *(const unsigned*)&cBl[n * SA + kk + 2 * t + 8];
            }
#pragma unroll
            for (int mt = 0; mt < 4; mt++) {
                int m = wm + mt * 16 + g;
                unsigned a0 = *(const unsigned*)&cA[m * SA + kk + 2 * t];
                unsigned a1 = *(const unsigned*)&cA[(m + 8) * SA + kk + 2 * t];
                unsigned a2 = *(const unsigned*)&cA[m * SA + kk + 2 * t + 8];
                unsigned a3 = *(const unsigned*)&cA[(m + 8) * SA + kk + 2 * t + 8];
#pragma unroll
                for (int nt = 0; nt < NT; nt++) {
                    mma_f16(acc[mt][nt], a0, a1, a2, a3, bh[nt][0], bh[nt][1]);
                    mma_f16(acc[mt][nt], a0, a1, a2, a3, bl[nt][0], bl[nt][1]);
                }
            }
        }
        if (s < 3) {
            storeTiles(1 - buf);
            __syncthreads();
        }
    }

#pragma unroll
    for (int mt = 0; mt < 4; mt++) {
        int r0 = m0 + wm + mt * 16 + g, r1 = r0 + 8;
        float n0 = (r0 < NN) ? g_norm[r0] : 0.f;
        float n1 = (r1 < NN) ? g_norm[r1] : 0.f;
#pragma unroll
        for (int nt = 0; nt < NT; nt++) {
            int col = wn + nt * 8 + 2 * t;
            if (r0 < NN) {
                __half2 h = __floats2half2_rn(acc[mt][nt][0] * n0, acc[mt][nt][1] * n0);
                *(__half2*)(Yh + (size_t)r0 * BN + col) = h;
            }
            if (r1 < NN) {
                __half2 h = __floats2half2_rn(acc[mt][nt][2] * n1, acc[mt][nt][3] * n1);
                *(__half2*)(Yh + (size_t)r1 * BN + col) = h;
            }
        }
    }
}

// ---------------- Aggregation: one warp per node, unroll-8 fp16 gather ----------
// o = norm[n]*(y[n] + sum y[src]) + bias
// MODE 0: leaky(o) -> half buffer   MODE 1: x=(x+leaky(o))/2 fp16 in place
// MODE 3: MODE 1 + unrounded fp32 mirror to out2
template <int MODE>
__global__ __launch_bounds__(128) void agg_kernel(const __half* __restrict__ Yh,
                                                  const float* __restrict__ bias,
                                                  __half* __restrict__ xbuf,
                                                  float* __restrict__ out2) {
    int gw = (blockIdx.x * 128 + threadIdx.x) >> 5;
    if (gw >= NN) return;
    int lane = threadIdx.x & 31;
    int beg = g_rowptr[gw], end = g_rowptr[gw + 1];
    float nm = g_norm[gw];
    const int* __restrict__ col = g_col;
    const uint2* Y4 = (const uint2*)Yh;
    uint2 sv = Y4[(size_t)gw * 32 + lane];
    float2 f0 = u2f2(sv.x), f1 = u2f2(sv.y);
    float4 acc = make_float4(f0.x, f0.y, f1.x, f1.y);
    int e = beg;
#define ACCV(vv) { float2 p_ = u2f2(vv.x), q_ = u2f2(vv.y); \
                   acc.x += p_.x; acc.y += p_.y; acc.z += q_.x; acc.w += q_.y; }
    for (; e + 7 < end; e += 8) {
        int s0 = col[e],     s1 = col[e + 1], s2 = col[e + 2], s3 = col[e + 3];
        int s4 = col[e + 4], s5 = col[e + 5], s6 = col[e + 6], s7 = col[e + 7];
        uint2 v0 = Y4[(size_t)s0 * 32 + lane];
        uint2 v1 = Y4[(size_t)s1 * 32 + lane];
        uint2 v2 = Y4[(size_t)s2 * 32 + lane];
        uint2 v3 = Y4[(size_t)s3 * 32 + lane];
        uint2 v4 = Y4[(size_t)s4 * 32 + lane];
        uint2 v5 = Y4[(size_t)s5 * 32 + lane];
        uint2 v6 = Y4[(size_t)s6 * 32 + lane];
        uint2 v7 = Y4[(size_t)s7 * 32 + lane];
        ACCV(v0) ACCV(v1) ACCV(v2) ACCV(v3)
        ACCV(v4) ACCV(v5) ACCV(v6) ACCV(v7)
    }
    for (; e + 1 < end; e += 2) {
        int s0 = col[e], s1 = col[e + 1];
        uint2 v0 = Y4[(size_t)s0 * 32 + lane];
        uint2 v1 = Y4[(size_t)s1 * 32 + lane];
        ACCV(v0) ACCV(v1)
    }
    if (e < end) {
        uint2 v = Y4[(size_t)col[e] * 32 + lane];
        ACCV(v)
    }
#undef ACCV
    float4 b = ((const float4*)bias)[lane];
    float4 o = make_float4(acc.x * nm + b.x, acc.y * nm + b.y,
                           acc.z * nm + b.z, acc.w * nm + b.w);
    size_t idx = (size_t)gw * 32 + lane;
    float4 l4 = make_float4(lk(o.x), lk(o.y), lk(o.z), lk(o.w));
    float4 nv;
    if constexpr (MODE == 0) {
        nv = l4;
    } else {
        uint2 xr = ((const uint2*)xbuf)[idx];
        float2 x0 = u2f2(xr.x), x1 = u2f2(xr.y);
        nv = make_float4((x0.x + l4.x) * 0.5f, (x0.y + l4.y) * 0.5f,
                         (x1.x + l4.z) * 0.5f, (x1.y + l4.w) * 0.5f);
        if constexpr (MODE == 3) ((float4*)out2)[idx] = nv;
    }
    uint2 p;
    __half2 h01 = __floats2half2_rn(nv.x, nv.y);
    __half2 h23 = __floats2half2_rn(nv.z, nv.w);
    p.x = *reinterpret_cast<unsigned*>(&h01);
    p.y = *reinterpret_cast<unsigned*>(&h23);
    ((uint2*)xbuf)[idx] = p;
}

// ---------------- final aggregation (output conv, D=64, no activation) --------
__global__ __launch_bounds__(128) void agg64_kernel(const __half* __restrict__ Yh,
                                                    const float* __restrict__ bias,
                                                    float* __restrict__ outp) {
    int gw = (blockIdx.x * 128 + threadIdx.x) >> 5;
    if (gw >= NN) return;
    int lane = threadIdx.x & 31;
    int beg = g_rowptr[gw], end = g_rowptr[gw + 1];
    float nm = g_norm[gw];
    const int* __restrict__ col = g_col;
    const unsigned* Y2 = (const unsigned*)Yh;
    float2 acc = u2f2(Y2[(size_t)gw * 32 + lane]);
    int e = beg;
    for (; e + 7 < end; e += 8) {
        int s0 = col[e],     s1 = col[e + 1], s2 = col[e + 2], s3 = col[e + 3];
        int s4 = col[e + 4], s5 = col[e + 5], s6 = col[e + 6], s7 = col[e + 7];
        float2 v0 = u2f2(Y2[(size_t)s0 * 32 + lane]);
        float2 v1 = u2f2(Y2[(size_t)s1 * 32 + lane]);
        float2 v2 = u2f2(Y2[(size_t)s2 * 32 + lane]);
        float2 v3 = u2f2(Y2[(size_t)s3 * 32 + lane]);
        float2 v4 = u2f2(Y2[(size_t)s4 * 32 + lane]);
        float2 v5 = u2f2(Y2[(size_t)s5 * 32 + lane]);
        float2 v6 = u2f2(Y2[(size_t)s6 * 32 + lane]);
        float2 v7 = u2f2(Y2[(size_t)s7 * 32 + lane]);
        acc.x += ((v0.x + v1.x) + (v2.x + v3.x)) + ((v4.x + v5.x) + (v6.x + v7.x));
        acc.y += ((v0.y + v1.y) + (v2.y + v3.y)) + ((v4.y + v5.y) + (v6.y + v7.y));
    }
    for (; e < end; e++) {
        float2 v = u2f2(Y2[(size_t)col[e] * 32 + lane]);
        acc.x += v.x; acc.y += v.y;
    }
    float2 b = ((const float2*)bias)[lane];
    ((float2*)outp)[(size_t)gw * 32 + lane] =
        make_float2(acc.x * nm + b.x, acc.y * nm + b.y);
}

// ---------------- launch ----------------
extern "C" void kernel_launch(void* const* d_in, const int* in_sizes, int n_in,
                              void* d_out, int out_size) {
    const float* inputs = (const float*)d_in[0];
    const int*   edges  = (const int*)d_in[1];
    const float* b_in   = (const float*)d_in[3];
    const float* b1     = (const float*)d_in[5];
    const float* b2     = (const float*)d_in[7];
    const float* b_out  = (const float*)d_in[9];
    float* out = (float*)d_out;

    const int* src = edges;
    const int* dst = edges + NE;

    void *pyh, *phh, *pxh, *pwh, *pwl, *pcnt;
    cudaGetSymbolAddress(&pyh, g_yh);
    cudaGetSymbolAddress(&phh, g_hh);
    cudaGetSymbolAddress(&pxh, g_xh);
    cudaGetSymbolAddress(&pwh, g_wh);
    cudaGetSymbolAddress(&pwl, g_wl);
    cudaGetSymbolAddress(&pcnt, g_cnt);
    __half* yh = (__half*)pyh;
    __half* hh = (__half*)phh;
    __half* xh = (__half*)pxh;
    __half* wh = (__half*)pwh;
    __half* wl = (__half*)pwl;

    // dynamic smem: 2 buffers of (A 128*40 + Bh BN*40 + Bl BN*40) halves
    const int SM128 = 2 * (128 * 40 + 2 * 128 * 40) * 2;  // 61440 B
    const int SM64  = 2 * (128 * 40 + 2 * 64 * 40) * 2;   // 40960 B
    cudaFuncSetAttribute(gemm_tc_kernel<128, float>,
                         cudaFuncAttributeMaxDynamicSharedMemorySize, SM128);
    cudaFuncSetAttribute(gemm_tc_kernel<128, __half>,
                         cudaFuncAttributeMaxDynamicSharedMemorySize, SM128);
    cudaFuncSetAttribute(gemm_tc_kernel<64, __half>,
                         cudaFuncAttributeMaxDynamicSharedMemorySize, SM64);

    const int GE = (NE + 255) / 256;
    const int GG = (NN + 127) / 128;       // gemm blocks
    const int GA = (NN * 32 + 127) / 128;  // agg blocks (warp/node, 128-thr blocks)
    const int GW = (NMAT * HD * HD + 255) / 256;
    const size_t WSTEP = (size_t)HD * HD;

    // weight split/transpose + CSR build
    prep_w_kernel<<<GW, 256>>>((const float*)d_in[2], (const float*)d_in[4],
                               (const float*)d_in[6], (const float*)d_in[8]);
    cudaMemsetAsync(pcnt, 0, NN * sizeof(int));
    count_kernel<<<GE, 256>>>(dst);
    scan_blocks_kernel<<<NSB, 1024>>>();
    scan_fix_kernel<<<NSB, 1024>>>();
    fill_kernel<<<GE, 256>>>(src, dst);

    // input conv
    gemm_tc_kernel<128, float><<<GG, 256, SM128>>>(inputs, wh, wl, yh);
    agg_kernel<0><<<GA, 128>>>(yh, b_in, xh, nullptr);

    // 6 residual blocks; last one mirrors fp32 x into d_out's second half
    for (int i = 0; i < 6; i++) {
        gemm_tc_kernel<128, __half><<<GG, 256, SM128>>>(xh, wh + (size_t)(1 + i) * WSTEP,
                                                        wl + (size_t)(1 + i) * WSTEP, yh);
        agg_kernel<0><<<GA, 128>>>(yh, b1 + (size_t)i * HD, hh, nullptr);
        gemm_tc_kernel<128, __half><<<GG, 256, SM128>>>(hh, wh + (size_t)(7 + i) * WSTEP,
                                                        wl + (size_t)(7 + i) * WSTEP, yh);
        if (i < 5)
            agg_kernel<1><<<GA, 128>>>(yh, b2 + (size_t)i * HD, xh, nullptr);
        else
            agg_kernel<3><<<GA, 128>>>(yh, b2 + (size_t)i * HD, xh,
                                       out + (size_t)NN * 64);
    }

    // output conv (no activation), writes first N*64 floats of d_out
    gemm_tc_kernel<64, __half><<<GG, 256, SM64>>>(xh, wh + (size_t)13 * WSTEP,
                                                  wl + (size_t)13 * WSTEP, yh);
    agg64_kernel<<<GA, 128>>>(yh, b_out, out);
}